// round 15
// baseline (speedup 1.0000x reference)
#include <cuda_runtime.h>
#include <cuda_fp16.h>
#include <cstdint>

#define DD   64
#define GSZ  (DD*DD*DD)
#define NMAX 65536
#define CC   32
#define FULLMASK 0xffffffffu
#define GRIDB 148
#define THR   512
#define CONV_THR 512
#define CONV_WARPS 16
#define NTAP_SEG 6
// smem byte layout for k_conv_m
#define OFFW 256
#define WTAPB 5120                      // per tap: hi 2560B + lo 2560B (32x40 halves)
#define OFFS (OFFW + NTAP_SEG * WTAPB)  // 30976
#define STAGEB 4608                     // 32 rows x 144B
#define SMEMB (OFFS + CONV_WARPS * 2 * STAGEB)   // 178432

// ---------------- device scratch ----------------
// Invariants at entry of every kernel_launch: g_grid all-zero, g_acc all-zero
// (k_epi restores both behind itself).
__device__ int    g_done;
__device__ int    g_bar;
__device__ int    g_grid[GSZ];                // 0 = empty, else m+1
__device__ int    g_coords[NMAX];
__device__ unsigned int g_pairs[27 * NMAX];   // bucket t: (src<<16)|m
__device__ int    g_cnt[27 * 32];
__device__ int    g_tilebase[28];
__device__ float  g_acc[NMAX * CC];
__device__ __half g_fh[NMAX * 64];            // per point: [32 hi][32 lo]

// ---------------- helpers ----------------
__device__ __forceinline__ void red4(float* p, float a, float b, float c, float d) {
    asm volatile("red.global.add.v4.f32 [%0], {%1, %2, %3, %4};"
                 :: "l"(p), "f"(a), "f"(b), "f"(c), "f"(d) : "memory");
}
__device__ __forceinline__ void cp16b(void* smem_dst, const void* gsrc) {
    unsigned d = (unsigned)__cvta_generic_to_shared(smem_dst);
    asm volatile("cp.async.cg.shared.global [%0], [%1], 16;" :: "r"(d), "l"(gsrc));
}
#define CP_COMMIT() asm volatile("cp.async.commit_group;" ::: "memory")
#define CP_WAIT1()  asm volatile("cp.async.wait_group 1;" ::: "memory")

__device__ __forceinline__ void ldsm4(uint32_t& r0, uint32_t& r1, uint32_t& r2,
                                      uint32_t& r3, uint32_t addr) {
    asm volatile("ldmatrix.sync.aligned.m8n8.x4.shared.b16 {%0,%1,%2,%3}, [%4];"
                 : "=r"(r0), "=r"(r1), "=r"(r2), "=r"(r3) : "r"(addr));
}
__device__ __forceinline__ void mma16816(float& d0, float& d1, float& d2, float& d3,
                                         uint32_t a0, uint32_t a1, uint32_t a2, uint32_t a3,
                                         uint32_t b0, uint32_t b1) {
    asm volatile("mma.sync.aligned.m16n8k16.row.col.f32.f16.f16.f32 "
                 "{%0,%1,%2,%3}, {%4,%5,%6,%7}, {%8,%9}, {%0,%1,%2,%3};"
                 : "+f"(d0), "+f"(d1), "+f"(d2), "+f"(d3)
                 : "r"(a0), "r"(a1), "r"(a2), "r"(a3), "r"(b0), "r"(b1));
}
__device__ __forceinline__ void sts2(uint32_t addr, float a, float b) {
    asm volatile("st.shared.v2.f32 [%0], {%1,%2};" :: "r"(addr), "f"(a), "f"(b) : "memory");
}

__device__ __forceinline__ void grid_barrier() {
    __syncthreads();
    if (threadIdx.x == 0) {
        __threadfence();
        int ticket = atomicAdd(&g_bar, 1);
        int target = (ticket / GRIDB + 1) * GRIDB;
        volatile int* vb = &g_bar;
        while (*vb < target) { }
    }
    __syncthreads();
}

// ---------------- prep: convert feats + fill -> (barrier) -> pairs + prefix ----------------
__global__ __launch_bounds__(THR, 1)
void k_prep(const void* __restrict__ idx, const float* __restrict__ values, int N) {
    int tid = threadIdx.x;
    int gt  = blockIdx.x * THR + tid;

    if (gt < 27 * 32) g_cnt[gt] = 0;
    if (gt == 0) g_done = 0;

    // convert layer-1 features to half hi/lo
    for (int i = gt; i < N * CC; i += GRIDB * THR) {
        float v = values[i];
        __half h = __float2half_rn(v);
        __half l = __float2half_rn(v - __half2float(h));
        int m = i >> 5, c = i & 31;
        g_fh[m * 64 + c] = h;
        g_fh[m * 64 + 32 + c] = l;
    }

    // per-block dtype detection: int64 layout -> odd 32-bit words all zero
    __shared__ int s_is64;
    {
        int v = (tid < 256) ? ((const int*)idx)[2 * tid + 1] : 0;
        int any = __syncthreads_count(v != 0);
        if (tid == 0) s_is64 = (any == 0) ? 1 : 0;
    }
    __syncthreads();
    int is64 = s_is64;

    // fill grid (single pass: N <= GRIDB*THR). Sentinel: m+1, 0=empty.
    int m = gt;
    int cp = 0;
    if (m < N) {
        int z, y, x;
        if (is64) {
            const long long* p = (const long long*)idx;
            z = (int)p[m * 4 + 1]; y = (int)p[m * 4 + 2]; x = (int)p[m * 4 + 3];
        } else {
            const int* p = (const int*)idx;
            z = p[m * 4 + 1]; y = p[m * 4 + 2]; x = p[m * 4 + 3];
        }
        cp = (z << 12) | (y << 6) | x;
        g_coords[m] = cp;
        g_grid[cp] = m + 1;
    }
    grid_barrier();

    bool active = (m < N);
    int vv[3] = { (cp >> 12) & 63, (cp >> 6) & 63, cp & 63 };
    bool inter = true;
    int ti[3][3], sv[3][3];
#pragma unroll
    for (int a = 0; a < 3; a++) {
        int v = vv[a];
        if (v == 0) {
            inter = false;
            ti[a][0] = 0; sv[a][0] = 0;
            ti[a][1] = 0; sv[a][1] = 1;
            ti[a][2] = 1; sv[a][2] = 0;
        } else if (v == DD - 1) {
            inter = false;
            ti[a][0] = 2; sv[a][0] = DD - 2;
            ti[a][1] = 2; sv[a][1] = DD - 1;
            ti[a][2] = 1; sv[a][2] = DD - 1;
        } else {
            ti[a][0] = 0; sv[a][0] = v + 1;
            ti[a][1] = 1; sv[a][1] = v;
            ti[a][2] = 2; sv[a][2] = v - 1;
        }
    }
    int lane = tid & 31;
    int slot = 0;
#pragma unroll
    for (int a = 0; a < 3; a++)
#pragma unroll
        for (int b = 0; b < 3; b++)
#pragma unroll
            for (int c = 0; c < 3; c++) {
                int t   = ti[0][a] * 9 + ti[1][b] * 3 + ti[2][c];
                int lin = (sv[0][a] << 12) | (sv[1][b] << 6) | sv[2][c];
                int src = active ? (g_grid[lin] - 1) : -1;
                bool present = (src >= 0);
                bool fast = inter && present;   // t == slot here
                unsigned bal = __ballot_sync(FULLMASK, fast);
                int ldr = bal ? (__ffs(bal) - 1) : 0;
                int base = 0;
                if (bal && lane == ldr) base = atomicAdd(&g_cnt[slot * 32], __popc(bal));
                base = __shfl_sync(FULLMASK, base, ldr);
                int pos = 0;
                if (fast)          pos = base + __popc(bal & ((1u << lane) - 1u));
                else if (present)  pos = atomicAdd(&g_cnt[t * 32], 1);
                if (present) g_pairs[t * NMAX + pos] = ((unsigned)src << 16) | (unsigned)m;
                slot++;
            }

    __shared__ int s_last;
    __threadfence();
    __syncthreads();
    if (tid == 0)
        s_last = (atomicAdd(&g_done, 1) == GRIDB - 1) ? 1 : 0;
    __syncthreads();
    if (s_last && tid < 32) {
        int ln = tid;
        int c = (ln < 27) ? g_cnt[ln * 32] : 0;
        int tiles = (c + 31) >> 5;
        int incl = tiles;
#pragma unroll
        for (int o = 1; o < 32; o <<= 1) {
            int v = __shfl_up_sync(FULLMASK, incl, o);
            if (ln >= o) incl += v;
        }
        if (ln < 27) g_tilebase[ln] = incl - tiles;
        if (ln == 31) g_tilebase[27] = incl;
    }
}

// ---------------- mma conv: 32-pt tiles, hi/lo half, explicit ldmatrix + mma.sync ----------------
__global__ __launch_bounds__(CONV_THR, 1)
void k_conv_m(const float* __restrict__ kern) {
    extern __shared__ char smc[];
    int* s_tb  = (int*)smc;        // 28
    int* s_cnt = s_tb + 28;        // 27
    int tid = threadIdx.x;
    if (tid < 28) s_tb[tid] = g_tilebase[tid];
    else if (tid < 55) s_cnt[tid - 28] = g_cnt[(tid - 28) * 32];
    __syncthreads();

    int total = s_tb[27];
    int c0 = (int)(((long long)total * blockIdx.x) / gridDim.x);
    int c1 = (int)(((long long)total * (blockIdx.x + 1)) / gridDim.x);
    if (c0 >= c1) return;

    int t_lo = 0;
    while (t_lo < 26 && c0 >= s_tb[t_lo + 1]) t_lo++;
    int t_hi = t_lo;
    while (t_hi < 26 && (c1 - 1) >= s_tb[t_hi + 1]) t_hi++;

    int lane = tid & 31;
    int wloc = tid >> 5;
    char* wbase  = smc + OFFW;
    char* stage0 = smc + OFFS + wloc * (2 * STAGEB);
    char* stage1 = stage0 + STAGEB;
    uint32_t stg0_u = (uint32_t)__cvta_generic_to_shared(stage0);
    uint32_t stg1_u = stg0_u + STAGEB;
    uint32_t wb_u   = (uint32_t)__cvta_generic_to_shared(wbase);
    int grow = lane >> 3, gc = lane & 7;
    int g8 = lane >> 2, tg = lane & 3;

    // lane-invariant A-ldmatrix address part: row = (lane&7) + ((lane>>3)&1)*8, col16 = (lane>>4)*16
    uint32_t aoff = (uint32_t)(((lane & 7) + ((grow & 1) << 3)) * 144 + ((lane >> 4) << 4));
    // B-ldmatrix lane offset: row = (lane&7) within ni-block, colb = (lane>>3)*16
    uint32_t boff = (uint32_t)((lane & 7) * 80 + (grow << 4));
    // D store lane offset: row g8, col 2*tg floats
    uint32_t doff = (uint32_t)(g8 * 144 + tg * 8);

    for (int seg = t_lo; seg <= t_hi; seg += NTAP_SEG) {
        int segHi = min(seg + NTAP_SEG - 1, t_hi);
        __syncthreads();
        // weights f32 [t][ci][co] -> half hi/lo wt[co*40+ci] (n-major rows = B col-major frags)
        int nel = (segHi - seg + 1) << 10;
        for (int i = tid; i < nel; i += CONV_THR) {
            int tr = i >> 10, r = i & 1023;
            int ci = r >> 5, co = r & 31;
            float v = kern[((seg + tr) << 10) + r];
            __half h = __float2half_rn(v);
            __half l = __float2half_rn(v - __half2float(h));
            __half* wt = (__half*)(wbase + tr * WTAPB);
            wt[co * 40 + ci] = h;
            wt[1280 + co * 40 + ci] = l;
        }
        __syncthreads();

        int r0 = max(c0, s_tb[seg]);
        int r1 = min(c1, s_tb[segHi + 1]);

        int T = r0 + wloc;
        int t = seg, li = 0, cnt = 0;    unsigned pw = 0;
        int t2 = seg, li2 = 0, cnt2 = 0; unsigned pw2 = 0;
        int cur = 0;
        int tw = -1;
        uint32_t BH[4][4], BL[4][4];   // [ni][ki0b0,ki0b1,ki1b0,ki1b1]

        if (T < r1) {
            while (t < segHi && T >= s_tb[t + 1]) t++;
            li = T - s_tb[t]; cnt = s_cnt[t];
            int idx = (li << 5) + lane;
            pw = (idx < cnt) ? g_pairs[t * NMAX + idx] : 0u;
#pragma unroll
            for (int i = 0; i < 8; i++) {
                unsigned pr = __shfl_sync(FULLMASK, pw, 4 * i + grow);
                cp16b(stage0 + (4 * i + grow) * 144 + gc * 16,
                      (const char*)(g_fh + (size_t)(pr >> 16) * 64) + gc * 16);
            }
            CP_COMMIT();
            int Tn = T + CONV_WARPS;
            if (Tn < r1) {
                t2 = t;
                while (t2 < segHi && Tn >= s_tb[t2 + 1]) t2++;
                li2 = Tn - s_tb[t2]; cnt2 = s_cnt[t2];
                int idx2 = (li2 << 5) + lane;
                pw2 = (idx2 < cnt2) ? g_pairs[t2 * NMAX + idx2] : 0u;
            }
        }

        while (T < r1) {
            int Tn = T + CONV_WARPS;
            if (Tn < r1) {
                char* nb = cur ? stage0 : stage1;
#pragma unroll
                for (int i = 0; i < 8; i++) {
                    unsigned pr = __shfl_sync(FULLMASK, pw2, 4 * i + grow);
                    cp16b(nb + (4 * i + grow) * 144 + gc * 16,
                          (const char*)(g_fh + (size_t)(pr >> 16) * 64) + gc * 16);
                }
            }
            CP_COMMIT();

            // prefetch T+2 metadata
            int t3 = t2, li3 = 0, cnt3 = 0; unsigned pw3 = 0;
            int Tnn = Tn + CONV_WARPS;
            if (Tnn < r1) {
                while (t3 < segHi && Tnn >= s_tb[t3 + 1]) t3++;
                li3 = Tnn - s_tb[t3]; cnt3 = s_cnt[t3];
                int idx3 = (li3 << 5) + lane;
                pw3 = (idx3 < cnt3) ? g_pairs[t3 * NMAX + idx3] : 0u;
            }

            CP_WAIT1();
            __syncwarp();
            uint32_t stg_u = cur ? stg1_u : stg0_u;
            char*    stg   = cur ? (char*)stage1 : (char*)stage0;

            // B frags (per-tap persistent, 8 ldmatrix.x4)
            if (t != tw) {
                uint32_t wt_u = wb_u + (uint32_t)((t - seg) * WTAPB);
#pragma unroll
                for (int ni = 0; ni < 4; ni++) {
                    uint32_t a = wt_u + (uint32_t)(ni * 8 * 80) + boff;
                    ldsm4(BH[ni][0], BH[ni][1], BH[ni][2], BH[ni][3], a);
                    ldsm4(BL[ni][0], BL[ni][1], BL[ni][2], BL[ni][3], a + 2560);
                }
                tw = t;
            }

            // compute per m-tile (16 rows), store D back into stage as f32
#pragma unroll
            for (int mi = 0; mi < 2; mi++) {
                uint32_t ab = stg_u + aoff + (uint32_t)(mi * 16 * 144);
                uint32_t AH[2][4], AL[2][4];
#pragma unroll
                for (int ki = 0; ki < 2; ki++) {
                    ldsm4(AH[ki][0], AH[ki][1], AH[ki][2], AH[ki][3], ab + ki * 32);
                    ldsm4(AL[ki][0], AL[ki][1], AL[ki][2], AL[ki][3], ab + ki * 32 + 64);
                }
#pragma unroll
                for (int ni = 0; ni < 4; ni++) {
                    float d0 = 0.f, d1 = 0.f, d2 = 0.f, d3 = 0.f;
#pragma unroll
                    for (int ki = 0; ki < 2; ki++) {
                        mma16816(d0, d1, d2, d3, AH[ki][0], AH[ki][1], AH[ki][2], AH[ki][3],
                                 BH[ni][2 * ki], BH[ni][2 * ki + 1]);
                        mma16816(d0, d1, d2, d3, AH[ki][0], AH[ki][1], AH[ki][2], AH[ki][3],
                                 BL[ni][2 * ki], BL[ni][2 * ki + 1]);
                        mma16816(d0, d1, d2, d3, AL[ki][0], AL[ki][1], AL[ki][2], AL[ki][3],
                                 BH[ni][2 * ki], BH[ni][2 * ki + 1]);
                    }
                    uint32_t da = stg_u + doff + (uint32_t)(mi * 16 * 144 + ni * 32);
                    sts2(da, d0, d1);
                    sts2(da + 8 * 144, d2, d3);
                }
            }
            __syncwarp();

            // scatter rows via red4
#pragma unroll
            for (int i = 0; i < 8; i++) {
                int fi = i * 32 + lane;
                int row = fi >> 3, q = fi & 7;
                unsigned prw = __shfl_sync(FULLMASK, pw, row);
                if (((li << 5) + row) < cnt) {
                    float4 v = *(float4*)(stg + row * 144 + q * 16);
                    red4(g_acc + (size_t)(prw & 0xffffu) * CC + q * 4, v.x, v.y, v.z, v.w);
                }
            }

            T = Tn; cur ^= 1;
            t = t2; li = li2; cnt = cnt2; pw = pw2;
            t2 = t3; li2 = li3; cnt2 = cnt3; pw2 = pw3;
        }
    }
}

// ---------------- epilogue: resets g_acc; optional g_fh emit / grid clear ----------------
__global__ void k_epi(const float* __restrict__ mask, const float* __restrict__ bias,
                      const float* __restrict__ resid, float* __restrict__ outp,
                      int N, int do_relu, int clear_grid, int write_fh) {
    int i = blockIdx.x * blockDim.x + threadIdx.x;
    if (i >= N * 8) return;
    int m = i >> 3, q = i & 7;
    float4 a = ((float4*)g_acc)[i];
    float mk = mask[m];
    float4 b = ((const float4*)bias)[q];
    float4 o;
    o.x = (a.x + mk * b.x) * mk;
    o.y = (a.y + mk * b.y) * mk;
    o.z = (a.z + mk * b.z) * mk;
    o.w = (a.w + mk * b.w) * mk;
    if (do_relu) {
        o.x = fmaxf(o.x, 0.f); o.y = fmaxf(o.y, 0.f);
        o.z = fmaxf(o.z, 0.f); o.w = fmaxf(o.w, 0.f);
    }
    if (resid) {
        float4 r = ((const float4*)resid)[i];
        o.x += r.x; o.y += r.y; o.z += r.z; o.w += r.w;
    }
    if (write_fh) {
        float hx = __half2float(__float2half_rn(o.x));
        float hy = __half2float(__float2half_rn(o.y));
        float hz = __half2float(__float2half_rn(o.z));
        float hw = __half2float(__float2half_rn(o.w));
        __half2* ph = (__half2*)(g_fh + (size_t)m * 64 + q * 4);
        ph[0] = __floats2half2_rn(o.x, o.y);
        ph[1] = __floats2half2_rn(o.z, o.w);
        __half2* pl = (__half2*)(g_fh + (size_t)m * 64 + 32 + q * 4);
        pl[0] = __floats2half2_rn(o.x - hx, o.y - hy);
        pl[1] = __floats2half2_rn(o.z - hz, o.w - hw);
    }
    if (outp) ((float4*)outp)[i] = o;
    ((float4*)g_acc)[i] = make_float4(0.f, 0.f, 0.f, 0.f);
    if (clear_grid && q == 0) g_grid[g_coords[m]] = 0;
}

// ---------------- launch ----------------
extern "C" void kernel_launch(void* const* d_in, const int* in_sizes, int n_in,
                              void* d_out, int out_size)
{
    const float* values = (const float*)d_in[0];
    const void*  indices = d_in[1];
    const float* mask   = (const float*)d_in[2];
    const float* kern1  = (const float*)d_in[3];
    const float* bias1  = (const float*)d_in[4];
    const float* kern2  = (const float*)d_in[5];
    const float* bias2  = (const float*)d_in[6];
    float* out = (float*)d_out;

    int N = in_sizes[0] / CC;
    if (N > NMAX) N = NMAX;

    static int smem_set = 0;
    if (!smem_set) {
        cudaFuncSetAttribute(k_conv_m, cudaFuncAttributeMaxDynamicSharedMemorySize, SMEMB);
        smem_set = 1;
    }

    k_prep<<<GRIDB, THR>>>(indices, values, N);
    k_conv_m<<<GRIDB, CONV_THR, SMEMB>>>(kern1);
    k_epi<<<(N * 8 + 511) / 512, 512>>>(mask, bias1, nullptr, nullptr, N, 1, 1, 1);
    k_conv_m<<<GRIDB, CONV_THR, SMEMB>>>(kern2);
    k_epi<<<(N * 8 + 511) / 512, 512>>>(mask, bias2, values, out, N, 0, 0, 0);
}

// round 16
// speedup vs baseline: 1.0652x; 1.0652x over previous
#include <cuda_runtime.h>
#include <cuda_fp16.h>
#include <mma.h>
#include <cstdint>

using namespace nvcuda;

#define DD   64
#define GSZ  (DD*DD*DD)
#define NMAX 65536
#define CC   32
#define FULLMASK 0xffffffffu
#define GRIDB 148
#define THR   512
#define CONV_THR 384
#define CONV_WARPS 12
#define NTAP_SEG 6
// smem byte layout for k_conv_w
#define OFFW 256
#define WTAPB 5120                      // per tap: hi 2560B + lo 2560B (32x40 halves)
#define OFFS (OFFW + NTAP_SEG * WTAPB)  // 30976
#define STAGEB 4608                     // 32 rows x 144B
#define SMEMB (OFFS + CONV_WARPS * 2 * STAGEB)   // 141568

// ---------------- device scratch ----------------
// Invariants at entry of every kernel_launch: g_grid all-zero, g_acc all-zero
// (k_epi restores both behind itself). g_bar is a monotone ticket.
__device__ int    g_bar;
__device__ int    g_grid[GSZ];                // 0 = empty, else m+1
__device__ int    g_coords[NMAX];
__device__ unsigned int g_pairs[27 * NMAX];   // bucket t: (src<<16)|m
__device__ int    g_cnt[27 * 32];             // padded counters (stride 32)
__device__ float  g_acc[NMAX * CC];
__device__ __half g_fh[NMAX * 64];            // per point: [32 hi][32 lo]

// ---------------- helpers ----------------
__device__ __forceinline__ void red4(float* p, float a, float b, float c, float d) {
    asm volatile("red.global.add.v4.f32 [%0], {%1, %2, %3, %4};"
                 :: "l"(p), "f"(a), "f"(b), "f"(c), "f"(d) : "memory");
}
__device__ __forceinline__ void cp16b(void* smem_dst, const void* gsrc) {
    unsigned d = (unsigned)__cvta_generic_to_shared(smem_dst);
    asm volatile("cp.async.cg.shared.global [%0], [%1], 16;" :: "r"(d), "l"(gsrc));
}
#define CP_COMMIT() asm volatile("cp.async.commit_group;" ::: "memory")
#define CP_WAIT1()  asm volatile("cp.async.wait_group 1;" ::: "memory")

__device__ __forceinline__ void grid_barrier() {
    __syncthreads();
    if (threadIdx.x == 0) {
        __threadfence();
        int ticket = atomicAdd(&g_bar, 1);
        int target = (ticket / GRIDB + 1) * GRIDB;
        volatile int* vb = &g_bar;
        while (*vb < target) { }
    }
    __syncthreads();
}

// ---------------- prep: atomic-free pair building ----------------
__global__ __launch_bounds__(THR, 1)
void k_prep(const void* __restrict__ idx, const float* __restrict__ values, int N) {
    int tid = threadIdx.x;
    int gt  = blockIdx.x * THR + tid;
    int wid = tid >> 5, lane = tid & 31;
    unsigned ltmask = (1u << lane) - 1u;

    __shared__ int w_cnt[16][28];     // per-warp per-tap counts / running offsets
    __shared__ int s_wbase[16][28];   // exclusive warp prefix within block
    __shared__ int s_bbase[28];       // block base in global bucket
    __shared__ int s_is64;

    if (gt < 27 * 32) g_cnt[gt] = 0;
    if (tid < 16 * 28) ((int*)w_cnt)[tid] = 0;

    // convert layer-1 features to half hi/lo
    for (int i = gt; i < N * CC; i += GRIDB * THR) {
        float v = values[i];
        __half h = __float2half_rn(v);
        __half l = __float2half_rn(v - __half2float(h));
        int m = i >> 5, c = i & 31;
        g_fh[m * 64 + c] = h;
        g_fh[m * 64 + 32 + c] = l;
    }

    // per-block dtype detection: int64 layout -> odd 32-bit words all zero
    {
        int v = (tid < 256) ? ((const int*)idx)[2 * tid + 1] : 0;
        int any = __syncthreads_count(v != 0);
        if (tid == 0) s_is64 = (any == 0) ? 1 : 0;
    }
    __syncthreads();
    int is64 = s_is64;

    // fill grid (single pass: N <= GRIDB*THR). Sentinel: m+1, 0=empty.
    int m = gt;
    int cp = 0;
    if (m < N) {
        int z, y, x;
        if (is64) {
            const long long* p = (const long long*)idx;
            z = (int)p[m * 4 + 1]; y = (int)p[m * 4 + 2]; x = (int)p[m * 4 + 3];
        } else {
            const int* p = (const int*)idx;
            z = p[m * 4 + 1]; y = p[m * 4 + 2]; x = p[m * 4 + 3];
        }
        cp = (z << 12) | (y << 6) | x;
        g_coords[m] = cp;
        g_grid[cp] = m + 1;
    }
    grid_barrier();   // resets (g_cnt) and grid fill visible everywhere

    // ---- enumerate neighbors once; cache srcs in registers ----
    bool active = (m < N);
    int vv[3] = { (cp >> 12) & 63, (cp >> 6) & 63, cp & 63 };
    int ti[3][3], sv[3][3];
#pragma unroll
    for (int a = 0; a < 3; a++) {
        int v = vv[a];
        if (v == 0) {
            ti[a][0] = 0; sv[a][0] = 0;
            ti[a][1] = 0; sv[a][1] = 1;
            ti[a][2] = 1; sv[a][2] = 0;
        } else if (v == DD - 1) {
            ti[a][0] = 2; sv[a][0] = DD - 2;
            ti[a][1] = 2; sv[a][1] = DD - 1;
            ti[a][2] = 1; sv[a][2] = DD - 1;
        } else {
            ti[a][0] = 0; sv[a][0] = v + 1;
            ti[a][1] = 1; sv[a][1] = v;
            ti[a][2] = 2; sv[a][2] = v - 1;
        }
    }
    int srcs[27];
    int taps[27];
    {
        int slot = 0;
#pragma unroll
        for (int a = 0; a < 3; a++)
#pragma unroll
            for (int b = 0; b < 3; b++)
#pragma unroll
                for (int c = 0; c < 3; c++) {
                    int lin = (sv[0][a] << 12) | (sv[1][b] << 6) | sv[2][c];
                    srcs[slot] = active ? (g_grid[lin] - 1) : -1;
                    taps[slot] = ti[0][a] * 9 + ti[1][b] * 3 + ti[2][c];
                    slot++;
                }
    }

    // ---- pass A: warp-private counts (zero atomics) ----
#pragma unroll
    for (int slot = 0; slot < 27; slot++) {
        bool present = srcs[slot] >= 0;
        int t = taps[slot];
        int key = present ? t : (32 + lane);
        unsigned grp = __match_any_sync(FULLMASK, key);
        if (present) {
            int ldr = __ffs(grp) - 1;
            if (lane == ldr) w_cnt[wid][t] += __popc(grp);
        }
    }
    __syncthreads();

    // ---- scan warps + one global atomic per tap per block ----
    if (tid < 27) {
        int acc = 0;
#pragma unroll
        for (int w = 0; w < 16; w++) {
            s_wbase[w][tid] = acc;
            acc += w_cnt[w][tid];
        }
        s_bbase[tid] = atomicAdd(&g_cnt[tid * 32], acc);
    }
    __syncthreads();
    if (tid < 16 * 28) ((int*)w_cnt)[tid] = 0;   // reuse as running offsets
    __syncthreads();

    // ---- pass B: write pairs at deterministic positions ----
#pragma unroll
    for (int slot = 0; slot < 27; slot++) {
        bool present = srcs[slot] >= 0;
        int t = taps[slot];
        int key = present ? t : (32 + lane);
        unsigned grp = __match_any_sync(FULLMASK, key);
        if (present) {
            int ldr = __ffs(grp) - 1;
            int rank = __popc(grp & ltmask);
            int off = w_cnt[wid][t];
            int pos = s_bbase[t] + s_wbase[wid][t] + off + rank;
            g_pairs[t * NMAX + pos] = ((unsigned)srcs[slot] << 16) | (unsigned)m;
            if (lane == ldr) w_cnt[wid][t] = off + __popc(grp);
        }
        __syncwarp();
    }
}

// ---------------- wmma conv (R12 core + local tile prefix) ----------------
__global__ __launch_bounds__(CONV_THR, 1)
void k_conv_w(const float* __restrict__ kern) {
    extern __shared__ char smc[];
    int* s_tb  = (int*)smc;        // 28
    int* s_cnt = s_tb + 28;        // 27
    int tid = threadIdx.x;
    if (tid < 32) {
        int c = (tid < 27) ? g_cnt[tid * 32] : 0;
        int tiles = (c + 31) >> 5;
        int incl = tiles;
#pragma unroll
        for (int o = 1; o < 32; o <<= 1) {
            int v = __shfl_up_sync(FULLMASK, incl, o);
            if (tid >= o) incl += v;
        }
        if (tid < 27) { s_tb[tid] = incl - tiles; s_cnt[tid] = c; }
        if (tid == 31) s_tb[27] = incl;
    }
    __syncthreads();

    int total = s_tb[27];
    int c0 = (int)(((long long)total * blockIdx.x) / gridDim.x);
    int c1 = (int)(((long long)total * (blockIdx.x + 1)) / gridDim.x);
    if (c0 >= c1) return;

    int t_lo = 0;
    while (t_lo < 26 && c0 >= s_tb[t_lo + 1]) t_lo++;
    int t_hi = t_lo;
    while (t_hi < 26 && (c1 - 1) >= s_tb[t_hi + 1]) t_hi++;

    int lane = tid & 31;
    int wloc = tid >> 5;
    char* wbase  = smc + OFFW;
    char* stage0 = smc + OFFS + wloc * (2 * STAGEB);
    char* stage1 = stage0 + STAGEB;
    int grow = lane >> 3, gc = lane & 7;

    for (int seg = t_lo; seg <= t_hi; seg += NTAP_SEG) {
        int segHi = min(seg + NTAP_SEG - 1, t_hi);
        __syncthreads();
        // weights f32 [t][ci][co] -> half hi/lo [co*40+ci] (col-major for wmma B)
        int nel = (segHi - seg + 1) << 10;
        for (int i = tid; i < nel; i += CONV_THR) {
            int tr = i >> 10, r = i & 1023;
            int ci = r >> 5, co = r & 31;
            float v = kern[((seg + tr) << 10) + r];
            __half h = __float2half_rn(v);
            __half l = __float2half_rn(v - __half2float(h));
            __half* wt = (__half*)(wbase + tr * WTAPB);
            wt[co * 40 + ci] = h;
            wt[1280 + co * 40 + ci] = l;
        }
        __syncthreads();

        int r0 = max(c0, s_tb[seg]);
        int r1 = min(c1, s_tb[segHi + 1]);

        int T = r0 + wloc;
        int t = seg, li = 0, cnt = 0;    unsigned pw = 0;
        int t2 = seg, li2 = 0, cnt2 = 0; unsigned pw2 = 0;
        int cur = 0;
        int tw = -1;
        wmma::fragment<wmma::matrix_b, 16, 16, 16, __half, wmma::col_major> bh[2][2], bl[2][2];

        if (T < r1) {
            while (t < segHi && T >= s_tb[t + 1]) t++;
            li = T - s_tb[t]; cnt = s_cnt[t];
            int idx = (li << 5) + lane;
            pw = (idx < cnt) ? g_pairs[t * NMAX + idx] : 0u;
#pragma unroll
            for (int i = 0; i < 8; i++) {
                unsigned pr = __shfl_sync(FULLMASK, pw, 4 * i + grow);
                cp16b(stage0 + (4 * i + grow) * 144 + gc * 16,
                      (const char*)(g_fh + (size_t)(pr >> 16) * 64) + gc * 16);
            }
            CP_COMMIT();
            int Tn = T + CONV_WARPS;
            if (Tn < r1) {
                t2 = t;
                while (t2 < segHi && Tn >= s_tb[t2 + 1]) t2++;
                li2 = Tn - s_tb[t2]; cnt2 = s_cnt[t2];
                int idx2 = (li2 << 5) + lane;
                pw2 = (idx2 < cnt2) ? g_pairs[t2 * NMAX + idx2] : 0u;
            }
        }

        while (T < r1) {
            int Tn = T + CONV_WARPS;
            if (Tn < r1) {
                char* nb = cur ? stage0 : stage1;
#pragma unroll
                for (int i = 0; i < 8; i++) {
                    unsigned pr = __shfl_sync(FULLMASK, pw2, 4 * i + grow);
                    cp16b(nb + (4 * i + grow) * 144 + gc * 16,
                          (const char*)(g_fh + (size_t)(pr >> 16) * 64) + gc * 16);
                }
            }
            CP_COMMIT();

            // prefetch T+2 metadata
            int t3 = t2, li3 = 0, cnt3 = 0; unsigned pw3 = 0;
            int Tnn = Tn + CONV_WARPS;
            if (Tnn < r1) {
                while (t3 < segHi && Tnn >= s_tb[t3 + 1]) t3++;
                li3 = Tnn - s_tb[t3]; cnt3 = s_cnt[t3];
                int idx3 = (li3 << 5) + lane;
                pw3 = (idx3 < cnt3) ? g_pairs[t3 * NMAX + idx3] : 0u;
            }

            CP_WAIT1();
            __syncwarp();
            char* stg = cur ? stage1 : stage0;

            // B frags (per-tap persistent)
            if (t != tw) {
                __half* whb = (__half*)(wbase + (t - seg) * WTAPB);
                __half* wlb = whb + 1280;
#pragma unroll
                for (int ki = 0; ki < 2; ki++)
#pragma unroll
                    for (int ni = 0; ni < 2; ni++) {
                        wmma::load_matrix_sync(bh[ki][ni], whb + ni * 16 * 40 + ki * 16, 40);
                        wmma::load_matrix_sync(bl[ki][ni], wlb + ni * 16 * 40 + ki * 16, 40);
                    }
                tw = t;
            }

            // A frags (hi at col 0, lo at col 32; pitch 72 halves)
            wmma::fragment<wmma::matrix_a, 16, 16, 16, __half, wmma::row_major> ah[2][2], al[2][2];
#pragma unroll
            for (int mi = 0; mi < 2; mi++)
#pragma unroll
                for (int ki = 0; ki < 2; ki++) {
                    wmma::load_matrix_sync(ah[mi][ki], (__half*)stg + mi * 16 * 72 + ki * 16, 72);
                    wmma::load_matrix_sync(al[mi][ki], (__half*)stg + mi * 16 * 72 + 32 + ki * 16, 72);
                }

            // 3-product hi/lo GEMM, store f32 back into stage (pitch 36 floats)
            wmma::fragment<wmma::accumulator, 16, 16, 16, float> acc;
#pragma unroll
            for (int mi = 0; mi < 2; mi++)
#pragma unroll
                for (int ni = 0; ni < 2; ni++) {
                    wmma::fill_fragment(acc, 0.f);
#pragma unroll
                    for (int ki = 0; ki < 2; ki++) {
                        wmma::mma_sync(acc, ah[mi][ki], bh[ki][ni], acc);
                        wmma::mma_sync(acc, ah[mi][ki], bl[ki][ni], acc);
                        wmma::mma_sync(acc, al[mi][ki], bh[ki][ni], acc);
                    }
                    wmma::store_matrix_sync((float*)stg + mi * 16 * 36 + ni * 16, acc, 36,
                                            wmma::mem_row_major);
                }
            __syncwarp();

            // scatter rows via red4
#pragma unroll
            for (int i = 0; i < 8; i++) {
                int fi = i * 32 + lane;
                int row = fi >> 3, q = fi & 7;
                unsigned prw = __shfl_sync(FULLMASK, pw, row);
                if (((li << 5) + row) < cnt) {
                    float4 v = *(float4*)(stg + row * 144 + q * 16);
                    red4(g_acc + (size_t)(prw & 0xffffu) * CC + q * 4, v.x, v.y, v.z, v.w);
                }
            }

            T = Tn; cur ^= 1;
            t = t2; li = li2; cnt = cnt2; pw = pw2;
            t2 = t3; li2 = li3; cnt2 = cnt3; pw2 = pw3;
        }
    }
}

// ---------------- epilogue: resets g_acc; optional g_fh emit / grid clear ----------------
__global__ void k_epi(const float* __restrict__ mask, const float* __restrict__ bias,
                      const float* __restrict__ resid, float* __restrict__ outp,
                      int N, int do_relu, int clear_grid, int write_fh) {
    int i = blockIdx.x * blockDim.x + threadIdx.x;
    if (i >= N * 8) return;
    int m = i >> 3, q = i & 7;
    float4 a = ((float4*)g_acc)[i];
    float mk = mask[m];
    float4 b = ((const float4*)bias)[q];
    float4 o;
    o.x = (a.x + mk * b.x) * mk;
    o.y = (a.y + mk * b.y) * mk;
    o.z = (a.z + mk * b.z) * mk;
    o.w = (a.w + mk * b.w) * mk;
    if (do_relu) {
        o.x = fmaxf(o.x, 0.f); o.y = fmaxf(o.y, 0.f);
        o.z = fmaxf(o.z, 0.f); o.w = fmaxf(o.w, 0.f);
    }
    if (resid) {
        float4 r = ((const float4*)resid)[i];
        o.x += r.x; o.y += r.y; o.z += r.z; o.w += r.w;
    }
    if (write_fh) {
        float hx = __half2float(__float2half_rn(o.x));
        float hy = __half2float(__float2half_rn(o.y));
        float hz = __half2float(__float2half_rn(o.z));
        float hw = __half2float(__float2half_rn(o.w));
        __half2* ph = (__half2*)(g_fh + (size_t)m * 64 + q * 4);
        ph[0] = __floats2half2_rn(o.x, o.y);
        ph[1] = __floats2half2_rn(o.z, o.w);
        __half2* pl = (__half2*)(g_fh + (size_t)m * 64 + 32 + q * 4);
        pl[0] = __floats2half2_rn(o.x - hx, o.y - hy);
        pl[1] = __floats2half2_rn(o.z - hz, o.w - hw);
    }
    if (outp) ((float4*)outp)[i] = o;
    ((float4*)g_acc)[i] = make_float4(0.f, 0.f, 0.f, 0.f);
    if (clear_grid && q == 0) g_grid[g_coords[m]] = 0;
}

// ---------------- launch ----------------
extern "C" void kernel_launch(void* const* d_in, const int* in_sizes, int n_in,
                              void* d_out, int out_size)
{
    const float* values = (const float*)d_in[0];
    const void*  indices = d_in[1];
    const float* mask   = (const float*)d_in[2];
    const float* kern1  = (const float*)d_in[3];
    const float* bias1  = (const float*)d_in[4];
    const float* kern2  = (const float*)d_in[5];
    const float* bias2  = (const float*)d_in[6];
    float* out = (float*)d_out;

    int N = in_sizes[0] / CC;
    if (N > NMAX) N = NMAX;

    static int smem_set = 0;
    if (!smem_set) {
        cudaFuncSetAttribute(k_conv_w, cudaFuncAttributeMaxDynamicSharedMemorySize, SMEMB);
        smem_set = 1;
    }

    k_prep<<<GRIDB, THR>>>(indices, values, N);
    k_conv_w<<<GRIDB, CONV_THR, SMEMB>>>(kern1);
    k_epi<<<(N * 8 + 511) / 512, 512>>>(mask, bias1, nullptr, nullptr, N, 1, 1, 1);
    k_conv_w<<<GRIDB, CONV_THR, SMEMB>>>(kern2);
    k_epi<<<(N * 8 + 511) / 512, 512>>>(mask, bias2, values, out, N, 0, 0, 0);
}